// round 3
// baseline (speedup 1.0000x reference)
#include <cuda_runtime.h>

#define BB 8
#define CIN 64
#define COUT 64
#define HH 128
#define WW 128
#define HW (HH*WW)
#define KK 9

// ---------------- scratch (no allocations allowed) ----------------
__device__ float g_offset[BB*18*HW];   // [b][2k+{dy,dx}][h][w]
__device__ float g_mask[BB*9*HW];      // [b][k][h][w]
__device__ float g_sum[COUT];
__device__ float g_sumsq[COUT];
__device__ float g_scale[COUT];
__device__ float g_shift[COUT];

// ---------------- kernel 0: zero stats ----------------
__global__ void k_zero() {
    int t = threadIdx.x;
    if (t < COUT) { g_sum[t] = 0.f; g_sumsq[t] = 0.f; }
}

// ---------------- kernel 1: offset (18ch) + mask (9ch) 3x3 conv, fused ----------------
// grid (8,8,8)=(tx,ty,b), block 256 = 16x16 pixels
#define SMEM1_FLOATS (CIN*KK*28 + 18*20)
__global__ __launch_bounds__(256) void k_offmask(
    const float* __restrict__ x,
    const float* __restrict__ off_w, const float* __restrict__ off_b,
    const float* __restrict__ mod_w, const float* __restrict__ mod_b)
{
    extern __shared__ float sm[];
    float* wsm = sm;                  // [c][k][28] (27 outputs + 1 pad)
    float* xs  = sm + CIN*KK*28;      // [18][20]

    const int tid = threadIdx.x;
    const int b = blockIdx.z;
    const int ty = tid >> 4, tx = tid & 15;
    const int gy = blockIdx.y*16 + ty;
    const int gx = blockIdx.x*16 + tx;

    // stage weights: wsm[(c*9+k)*28 + o]
    for (int idx = tid; idx < 27*CIN*KK; idx += 256) {
        int o = idx / (CIN*KK);
        int rem = idx - o*(CIN*KK);
        int c = rem / KK, k = rem - c*KK;
        float v = (o < 18) ? off_w[(o*CIN + c)*KK + k]
                           : mod_w[((o-18)*CIN + c)*KK + k];
        wsm[(c*KK + k)*28 + o] = v;
    }

    float acc[27];
#pragma unroll
    for (int o = 0; o < 27; o++) acc[o] = 0.f;

    const int gy0 = blockIdx.y*16 - 1;
    const int gx0 = blockIdx.x*16 - 1;

    for (int c = 0; c < CIN; c++) {
        __syncthreads();   // protect xs overwrite (and weight staging on iter 0)
        const float* xp = x + (size_t)(b*CIN + c)*HW;
        for (int idx = tid; idx < 18*18; idx += 256) {
            int r = idx / 18, cc = idx - r*18;
            int yy = gy0 + r, xx = gx0 + cc;
            float v = 0.f;
            if (yy >= 0 && yy < HH && xx >= 0 && xx < WW) v = xp[yy*WW + xx];
            xs[r*20 + cc] = v;
        }
        __syncthreads();
        float xv[9];
#pragma unroll
        for (int k = 0; k < 9; k++)
            xv[k] = xs[(ty + k/3)*20 + (tx + (k - (k/3)*3))];
#pragma unroll
        for (int k = 0; k < 9; k++) {
            const float4* wr = (const float4*)&wsm[(c*KK + k)*28];
            float wrow[28];
#pragma unroll
            for (int q = 0; q < 7; q++) ((float4*)wrow)[q] = wr[q];
            float xk = xv[k];
#pragma unroll
            for (int o = 0; o < 27; o++) acc[o] += xk * wrow[o];
        }
    }

    const int pix = gy*WW + gx;
#pragma unroll
    for (int o = 0; o < 18; o++)
        g_offset[(b*18 + o)*HW + pix] = acc[o] + off_b[o];
#pragma unroll
    for (int o = 0; o < 9; o++) {
        float t = acc[18 + o] + mod_b[o];
        g_mask[(b*9 + o)*HW + pix] = 2.f / (1.f + expf(-t));
    }
}

// ---------------- kernel 2: deform sample + einsum + BN partial sums ----------------
// grid (128 rows, 8 batch), block 512. One block = one output row (128 px, all 64 out ch).
#define SMEM2_FLOATS (COUT*576 + 2*9*128)
__global__ __launch_bounds__(512) void k_deform(
    const float* __restrict__ x,
    const float* __restrict__ w,
    const float* __restrict__ bias,
    float* __restrict__ out)
{
    extern __shared__ float sm[];
    float* Wsm = sm;                 // [o][576]  natural layout (broadcast LDS)
    float* vsm = sm + COUT*576;      // [2][9][128]

    const int tid  = threadIdx.x;
    const int y    = blockIdx.x;
    const int b    = blockIdx.y;
    const int warp = tid >> 5, lane = tid & 31;
    const int obase = warp * 4;      // 16 warps x 4 = 64 out channels
    const int pbase = lane * 4;      // 32 lanes x 4 = 128 pixels

    // stage W coalesced
    {
        const float4* src = (const float4*)w;
        float4* dst = (float4*)Wsm;
        for (int i = tid; i < COUT*576/4; i += 512) dst[i] = src[i];
    }

    // precompute my bilinear samples (channel-independent)
    int   sidx[3][4];
    float swt[3][4];
    int   sk[3], spx[3];
    bool  sval[3];
#pragma unroll
    for (int i = 0; i < 3; i++) {
        int sid = tid + 512*i;
        sval[i] = (sid < 1152);
        int k  = sval[i] ? (sid >> 7) : 0;
        int px = sid & 127;
        sk[i] = k; spx[i] = px;
        float dy = g_offset[(b*18 + 2*k  )*HW + y*WW + px];
        float dx = g_offset[(b*18 + 2*k+1)*HW + y*WW + px];
        float m  = g_mask  [(b*9  + k    )*HW + y*WW + px];
        if (!sval[i]) m = 0.f;
        float py  = dy + (float)(k/3 - 1) + (float)y;
        float pxf = dx + (float)(k - (k/3)*3 - 1) + (float)px;
        float fy = floorf(py), fx = floorf(pxf);
        float ly = py - fy, lx = pxf - fx;
        int y0 = (int)fy, x0 = (int)fx;
        int y1 = y0 + 1,  x1 = x0 + 1;
        float cw[4] = { (1.f-ly)*(1.f-lx)*m, (1.f-ly)*lx*m,
                        ly*(1.f-lx)*m,       ly*lx*m };
        int cy[4] = { y0, y0, y1, y1 };
        int cx[4] = { x0, x1, x0, x1 };
#pragma unroll
        for (int j = 0; j < 4; j++) {
            bool v = (cy[j] >= 0 && cy[j] < HH && cx[j] >= 0 && cx[j] < WW);
            int yc = min(max(cy[j], 0), HH-1);
            int xc = min(max(cx[j], 0), WW-1);
            sidx[i][j] = yc*WW + xc;
            swt[i][j]  = v ? cw[j] : 0.f;
        }
    }

    const float* xb = x + (size_t)b*CIN*HW;

    // gather c=0
    float gv[3][4];
#pragma unroll
    for (int i = 0; i < 3; i++)
#pragma unroll
        for (int j = 0; j < 4; j++) gv[i][j] = xb[sidx[i][j]];

    __syncthreads();   // W staged
#pragma unroll
    for (int i = 0; i < 3; i++) if (sval[i]) {
        float v = gv[i][0]*swt[i][0] + gv[i][1]*swt[i][1]
                + gv[i][2]*swt[i][2] + gv[i][3]*swt[i][3];
        vsm[(0*9 + sk[i])*128 + spx[i]] = v;
    }
    __syncthreads();

    float acc[4][4];
#pragma unroll
    for (int oi = 0; oi < 4; oi++)
#pragma unroll
        for (int p = 0; p < 4; p++) acc[oi][p] = 0.f;

    for (int c = 0; c < CIN; c++) {
        const int cur = c & 1, nxt = cur ^ 1;

        // issue gather loads for c+1 early (hidden under compute)
        if (c + 1 < CIN) {
            const float* xp = xb + (c+1)*HW;
#pragma unroll
            for (int i = 0; i < 3; i++)
#pragma unroll
                for (int j = 0; j < 4; j++) gv[i][j] = xp[sidx[i][j]];
        }

        // compute: acc[o][px] += v[k][px] * W[o][c*9+k]
        float4 v4[9];
#pragma unroll
        for (int k = 0; k < 9; k++)
            v4[k] = *(const float4*)&vsm[(cur*9 + k)*128 + pbase];
#pragma unroll
        for (int oi = 0; oi < 4; oi++) {
            const float* wr = &Wsm[(obase + oi)*576 + c*9];
#pragma unroll
            for (int k = 0; k < 9; k++) {
                float wv = wr[k];
                acc[oi][0] += v4[k].x * wv;
                acc[oi][1] += v4[k].y * wv;
                acc[oi][2] += v4[k].z * wv;
                acc[oi][3] += v4[k].w * wv;
            }
        }

        if (c + 1 < CIN) {
#pragma unroll
            for (int i = 0; i < 3; i++) if (sval[i]) {
                float v = gv[i][0]*swt[i][0] + gv[i][1]*swt[i][1]
                        + gv[i][2]*swt[i][2] + gv[i][3]*swt[i][3];
                vsm[(nxt*9 + sk[i])*128 + spx[i]] = v;
            }
        }
        __syncthreads();
    }

    // epilogue: bias, write y, per-channel partial sums
#pragma unroll
    for (int oi = 0; oi < 4; oi++) {
        int o = obase + oi;
        float bb = bias[o];
        float4 r;
        r.x = acc[oi][0] + bb; r.y = acc[oi][1] + bb;
        r.z = acc[oi][2] + bb; r.w = acc[oi][3] + bb;
        *(float4*)&out[(size_t)(b*COUT + o)*HW + y*WW + pbase] = r;

        float s  = r.x + r.y + r.z + r.w;
        float ss = r.x*r.x + r.y*r.y + r.z*r.z + r.w*r.w;
#pragma unroll
        for (int d = 16; d; d >>= 1) {
            s  += __shfl_xor_sync(0xffffffffu, s,  d);
            ss += __shfl_xor_sync(0xffffffffu, ss, d);
        }
        if (lane == 0) {
            atomicAdd(&g_sum[o], s);
            atomicAdd(&g_sumsq[o], ss);
        }
    }
}

// ---------------- kernel 3: BN finalize ----------------
__global__ void k_bnstats(const float* __restrict__ gamma, const float* __restrict__ beta) {
    int o = threadIdx.x;
    if (o < COUT) {
        const float n = (float)(BB*HW);
        float mean = g_sum[o] / n;
        float var  = g_sumsq[o] / n - mean*mean;
        var = fmaxf(var, 0.f);
        float sc = gamma[o] / sqrtf(var + 1e-5f);
        g_scale[o] = sc;
        g_shift[o] = beta[o] - mean*sc;
    }
}

// ---------------- kernel 4: normalize + relu, in place ----------------
__global__ void k_apply(float* __restrict__ out) {
    int i = blockIdx.x*blockDim.x + threadIdx.x;   // float4 index
    const int total = BB*COUT*HW/4;
    if (i < total) {
        int o = (i >> 12) & 63;   // 4096 float4 per channel plane
        float sc = g_scale[o], sh = g_shift[o];
        float4 v = ((float4*)out)[i];
        v.x = fmaxf(fmaf(v.x, sc, sh), 0.f);
        v.y = fmaxf(fmaf(v.y, sc, sh), 0.f);
        v.z = fmaxf(fmaf(v.z, sc, sh), 0.f);
        v.w = fmaxf(fmaf(v.w, sc, sh), 0.f);
        ((float4*)out)[i] = v;
    }
}

// ---------------- launcher ----------------
extern "C" void kernel_launch(void* const* d_in, const int* in_sizes, int n_in,
                              void* d_out, int out_size)
{
    const float* x     = (const float*)d_in[0];
    const float* off_w = (const float*)d_in[1];
    const float* off_b = (const float*)d_in[2];
    const float* mod_w = (const float*)d_in[3];
    const float* mod_b = (const float*)d_in[4];
    const float* w     = (const float*)d_in[5];
    const float* bias  = (const float*)d_in[6];
    const float* gamma = (const float*)d_in[7];
    const float* beta  = (const float*)d_in[8];
    float* out = (float*)d_out;

    const int smem1 = SMEM1_FLOATS * 4;
    const int smem2 = SMEM2_FLOATS * 4;
    cudaFuncSetAttribute(k_offmask, cudaFuncAttributeMaxDynamicSharedMemorySize, smem1);
    cudaFuncSetAttribute(k_deform,  cudaFuncAttributeMaxDynamicSharedMemorySize, smem2);

    k_zero<<<1, 64>>>();
    k_offmask<<<dim3(8,8,8), 256, smem1>>>(x, off_w, off_b, mod_w, mod_b);
    k_deform<<<dim3(128,8), 512, smem2>>>(x, w, bias, out);
    k_bnstats<<<1, 64>>>(gamma, beta);
    k_apply<<<8192, 256>>>(out);
}